// round 12
// baseline (speedup 1.0000x reference)
#include <cuda_runtime.h>
#include <cuda_fp16.h>
#include <cstdint>
#include <math.h>

// ---------------- problem dims (fixed) ----------------
#define HID   512
#define EXPD  2048
#define BATCH 4
#define SEQ   4096
#define M_TOT (BATCH*SEQ)      // 16384
#define NCH 64
#define CHL 64

// ---------------- scratch (device globals; 16B aligned) ----------------
__device__ __align__(16) __half g_xh  [(size_t)M_TOT*HID];
__device__ __align__(16) __half g_w1h [(size_t)EXPD*HID];
__device__ __align__(16) __half g_w2h [(size_t)EXPD*HID];
__device__ __align__(16) __half g_wzh [(size_t)EXPD*EXPD];
__device__ __align__(16) __half g_whh [(size_t)EXPD*EXPD];
__device__ __align__(16) __half g_woh [(size_t)HID*EXPD];
__device__ __align__(16) __half g_xin [(size_t)M_TOT*EXPD];
__device__ __align__(16) __half g_z   [(size_t)M_TOT*EXPD];
__device__ __align__(16) __half g_ht  [(size_t)M_TOT*EXPD];
__device__ __align__(16) __half g_xskip[(size_t)M_TOT*EXPD];
__device__ __align__(16) __half g_u   [(size_t)M_TOT*EXPD];
__device__ __align__(16) float g_aggA [(size_t)BATCH*NCH*EXPD];
__device__ __align__(16) float g_aggB [(size_t)BATCH*NCH*EXPD];
__device__ __align__(16) float g_carry[(size_t)BATCH*NCH*EXPD];

// ---------------- PTX helpers (base-target features only) ----------------
__device__ __forceinline__ uint32_t smem_u32(const void* p) {
    uint32_t a;
    asm("{ .reg .u64 t; cvta.to.shared.u64 t, %1; cvt.u32.u64 %0, t; }" : "=r"(a) : "l"(p));
    return a;
}
__device__ __forceinline__ void cp16(uint32_t dst, const void* src) {
    asm volatile("cp.async.cg.shared.global [%0], [%1], 16;" :: "r"(dst), "l"(src));
}
#define CP_COMMIT() asm volatile("cp.async.commit_group;" ::: "memory")
#define CP_WAIT(n)  asm volatile("cp.async.wait_group %0;" :: "n"(n) : "memory")

__device__ __forceinline__ void ldsm4(uint32_t* r, uint32_t addr) {
    asm volatile("ldmatrix.sync.aligned.m8n8.x4.shared.b16 {%0,%1,%2,%3}, [%4];"
        : "=r"(r[0]), "=r"(r[1]), "=r"(r[2]), "=r"(r[3]) : "r"(addr));
}
__device__ __forceinline__ void mma_f16(float* c, const uint32_t* a, const uint32_t* b) {
    asm volatile(
        "mma.sync.aligned.m16n8k16.row.col.f32.f16.f16.f32 "
        "{%0,%1,%2,%3}, {%4,%5,%6,%7}, {%8,%9}, {%0,%1,%2,%3};"
        : "+f"(c[0]), "+f"(c[1]), "+f"(c[2]), "+f"(c[3])
        : "r"(a[0]), "r"(a[1]), "r"(a[2]), "r"(a[3]), "r"(b[0]), "r"(b[1]));
}

// ---------------- mma.sync GEMM: C[M,N] = act(A[M,K] @ (B[N,K])^T + bias) ------
// fp16 x fp16 -> fp32 acc. 256 threads: 8 warps, 4m x 2n, warp tile 32x64.
// 2 CTAs/SM. All 6 ldsm per kk batched before MMAs; kk loop fully unrolled
// with no barriers so ptxas can software-pipeline ldsm across slices.
#define BM 128
#define BN 128
#define BK 64
#define NTHREADS 256
#define T_A 0
#define T_B 16384
#define STAGE_BYTES 32768
#define NSTAGE 3
#define SMEM_BYTES (NSTAGE*STAGE_BYTES)

// ACT: 0=none 1=silu 2=sigmoid ; OUT: 0 -> Cf fp32 ; 1 -> Ch fp16
template<int ACT, int OUT>
__global__ __launch_bounds__(NTHREADS, 2)
void gemm_mma(const __half* __restrict__ A, const __half* __restrict__ B,
              const float* __restrict__ bias,
              float* __restrict__ Cf, __half* __restrict__ Ch,
              int M, int N, int K)
{
    extern __shared__ char smem[];
    const uint32_t sb = smem_u32(smem);
    const int tid  = threadIdx.x;
    const int wid  = tid >> 5;
    const int lane = tid & 31;
    const int wm = wid >> 1;           // 0..3  -> m offset wm*32
    const int wn = wid & 1;            // 0..1  -> n offset wn*64
    const int bm = blockIdx.y * BM;
    const int bn = blockIdx.x * BN;

    const int Kv = K >> 3;             // row pitch in uint4 (8 fp16)
    const uint4* gA = (const uint4*)A;
    const uint4* gB = (const uint4*)B;

    const int nk = K / BK;

    // precomputed per-thread load addresses (advance by 8 uint4 per chunk)
    const int ldrow = tid >> 3, ldch = tid & 7;
    const uint32_t ldso = (uint32_t)(ldrow * 128 + ((ldch ^ (ldrow & 7)) << 4));

    auto load_stage = [&](int buf, int kc) {
        const int kv0 = kc * (BK / 8);
        const uint32_t base = sb + buf * STAGE_BYTES;
        #pragma unroll
        for (int t = 0; t < 4; t++) {           // A: 128 rows x 8 chunks
            int row = ldrow + t * 32;
            uint32_t so = ldso + (uint32_t)(t * 32 * 128);
            cp16(base + T_A + so, gA + (size_t)(bm + row) * Kv + kv0 + ldch);
        }
        #pragma unroll
        for (int t = 0; t < 4; t++) {           // B: 128 rows x 8 chunks
            int row = ldrow + t * 32;
            uint32_t so = ldso + (uint32_t)(t * 32 * 128);
            cp16(base + T_B + so, gB + (size_t)(bn + row) * Kv + kv0 + ldch);
        }
    };

    // precomputed fragment smem address components (row-dependent parts)
    uint32_t aBase[2], bBase[4];
    #pragma unroll
    for (int mi = 0; mi < 2; mi++) {
        int row = wm * 32 + mi * 16 + (lane & 15);
        aBase[mi] = (uint32_t)(row * 128) ^ ((uint32_t)(row & 7) << 4) ^ (((uint32_t)row & 7) << 4 ^ ((uint32_t)(row & 7) << 4)); // row*128 with mask folded below
        aBase[mi] = (uint32_t)(row * 128);
        aBase[mi] |= 0;  // keep simple; XOR applied with byteCol below
    }
    uint32_t aMask[2], bMask[4];
    #pragma unroll
    for (int mi = 0; mi < 2; mi++) {
        int row = wm * 32 + mi * 16 + (lane & 15);
        aBase[mi] = (uint32_t)(row * 128);
        aMask[mi] = ((uint32_t)(row & 7)) << 4;
    }
    #pragma unroll
    for (int nt = 0; nt < 4; nt++) {
        int row = wn * 64 + nt * 16 + (lane & 15);
        bBase[nt] = (uint32_t)(row * 128);
        bMask[nt] = ((uint32_t)(row & 7)) << 4;
    }
    const uint32_t laneCol = ((uint32_t)(lane >> 4)) << 4;

    float acc[2][8][4];
    #pragma unroll
    for (int mi = 0; mi < 2; mi++)
        #pragma unroll
        for (int ni = 0; ni < 8; ni++)
            #pragma unroll
            for (int q = 0; q < 4; q++)
                acc[mi][ni][q] = 0.f;

    load_stage(0, 0);
    CP_COMMIT();
    load_stage(1, 1);
    CP_COMMIT();

    for (int kc = 0; kc < nk; kc++) {
        const int buf = kc % NSTAGE;
        if (kc + 1 < nk) { CP_WAIT(1); } else { CP_WAIT(0); }
        __syncthreads();
        if (kc + 2 < nk) {
            load_stage((kc + 2) % NSTAGE, kc + 2);
            CP_COMMIT();
        }

        const uint32_t stA = sb + buf * STAGE_BYTES + T_A;
        const uint32_t stB = sb + buf * STAGE_BYTES + T_B;
        #pragma unroll
        for (int kk = 0; kk < BK / 16; kk++) {
            const uint32_t byteCol = (uint32_t)(kk * 32) + laneCol;
            // batch ALL fragment loads first (6 ldsm back-to-back)
            uint32_t ah[2][4], rb[4][4];
            #pragma unroll
            for (int mi = 0; mi < 2; mi++)
                ldsm4(ah[mi], stA + aBase[mi] + (byteCol ^ aMask[mi]));
            #pragma unroll
            for (int nt = 0; nt < 4; nt++)
                ldsm4(rb[nt], stB + bBase[nt] + (byteCol ^ bMask[nt]));
            // then all 16 MMAs
            #pragma unroll
            for (int nt = 0; nt < 4; nt++) {
                uint32_t b0[2] = { rb[nt][0], rb[nt][2] }, b1[2] = { rb[nt][1], rb[nt][3] };
                #pragma unroll
                for (int mi = 0; mi < 2; mi++) {
                    mma_f16(acc[mi][2*nt+0], ah[mi], b0);
                    mma_f16(acc[mi][2*nt+1], ah[mi], b1);
                }
            }
        }
    }

    // ---------------- epilogue: bias + activation + store ----------------
    const int qrow = lane >> 2;        // 0..7
    const int qcol = (lane & 3) * 2;   // 0,2,4,6
    #pragma unroll
    for (int mi = 0; mi < 2; mi++) {
        #pragma unroll
        for (int ni = 0; ni < 8; ni++) {
            const int n0 = bn + wn * 64 + ni * 8 + qcol;
            const float bias0 = bias[n0], bias1 = bias[n0 + 1];
            #pragma unroll
            for (int half_ = 0; half_ < 2; half_++) {
                const int m = bm + wm * 32 + mi * 16 + qrow + half_ * 8;
                float v0 = acc[mi][ni][half_ * 2 + 0] + bias0;
                float v1 = acc[mi][ni][half_ * 2 + 1] + bias1;
                if (ACT == 1) {
                    v0 *= 1.f / (1.f + expf(-v0));
                    v1 *= 1.f / (1.f + expf(-v1));
                } else if (ACT == 2) {
                    v0 = 1.f / (1.f + expf(-v0));
                    v1 = 1.f / (1.f + expf(-v1));
                }
                if (OUT == 1) {
                    __half h0 = __float2half_rn(v0);
                    __half h1 = __float2half_rn(v1);
                    uint32_t hp = (uint32_t)__half_as_ushort(h0) | ((uint32_t)__half_as_ushort(h1) << 16);
                    *(uint32_t*)&Ch[(size_t)m * N + n0] = hp;
                } else {
                    *(float2*)&Cf[(size_t)m * N + n0] = make_float2(v0, v1);
                }
            }
        }
    }
}

// ---------------- weight transpose: W[K,N] fp32 -> T[N,K] fp16 -------------
__global__ __launch_bounds__(256)
void transpose_h(const float* __restrict__ W, __half* __restrict__ T, int K, int N)
{
    __shared__ float t[32][33];
    const int n0 = blockIdx.x * 32, k0 = blockIdx.y * 32;
    const int tx = threadIdx.x & 31, ty0 = threadIdx.x >> 5;
    #pragma unroll
    for (int dy = 0; dy < 32; dy += 8)
        t[ty0 + dy][tx] = W[(size_t)(k0 + ty0 + dy) * N + n0 + tx];
    __syncthreads();
    #pragma unroll
    for (int dy = 0; dy < 32; dy += 8) {
        int ty = ty0 + dy;
        T[(size_t)(n0 + ty) * K + k0 + tx] = __float2half_rn(t[tx][ty]);
    }
}

// ---------------- x convert: fp32 -> fp16 ----------------
__global__ __launch_bounds__(256)
void convert_h(const float* __restrict__ x, __half* __restrict__ h, int n)
{
    int i = blockIdx.x * blockDim.x + threadIdx.x;
    if (i < n) h[i] = __float2half_rn(x[i]);
}

// ---------------- scan (minGRU linear recurrence), 3-pass chunked ----------------
__global__ __launch_bounds__(256)
void scan_pass1(const __half* __restrict__ z, const __half* __restrict__ ht,
                float* __restrict__ aggA, float* __restrict__ aggB)
{
    int t = blockIdx.x * blockDim.x + threadIdx.x;
    int f = t % EXPD, rc = t / EXPD, c = rc % NCH, bb = rc / NCH;
    size_t base = ((size_t)bb * SEQ + (size_t)c * CHL) * EXPD + f;
    float A = 1.f, B = 0.f;
    #pragma unroll 4
    for (int i = 0; i < CHL; i++) {
        size_t idx = base + (size_t)i * EXPD;
        float zi = __half2float(z[idx]), hi = __half2float(ht[idx]);
        float ai = 1.f - zi, bi = zi * hi;
        A = A * ai;
        B = B * ai + bi;
    }
    aggA[t] = A; aggB[t] = B;
}

__global__ __launch_bounds__(256)
void scan_pass2(const float* __restrict__ aggA, const float* __restrict__ aggB,
                float* __restrict__ carry)
{
    int t = blockIdx.x * blockDim.x + threadIdx.x;
    int f = t % EXPD, bb = t / EXPD;
    size_t base = (size_t)bb * NCH * EXPD + f;
    float h = 0.f;
    for (int c = 0; c < NCH; c++) {
        size_t idx = base + (size_t)c * EXPD;
        carry[idx] = h;
        h = aggA[idx] * h + aggB[idx];
    }
}

__global__ __launch_bounds__(256)
void scan_pass3(const __half* __restrict__ z, const __half* __restrict__ ht,
                const float* __restrict__ carry, const __half* __restrict__ xskip,
                __half* __restrict__ u)
{
    int t = blockIdx.x * blockDim.x + threadIdx.x;
    int f = t % EXPD, rc = t / EXPD, c = rc % NCH, bb = rc / NCH;
    size_t base = ((size_t)bb * SEQ + (size_t)c * CHL) * EXPD + f;
    float h = carry[t];
    #pragma unroll 4
    for (int i = 0; i < CHL; i++) {
        size_t idx = base + (size_t)i * EXPD;
        float zi = __half2float(z[idx]), hti = __half2float(ht[idx]);
        h = (1.f - zi) * h + zi * hti;
        u[idx] = __float2half_rn(__half2float(xskip[idx]) + h);
    }
}

// ---------------- launch ----------------
extern "C" void kernel_launch(void* const* d_in, const int* in_sizes, int n_in,
                              void* d_out, int out_size)
{
    const float* x     = (const float*)d_in[0];
    const float* W_in1 = (const float*)d_in[1];
    const float* b_in1 = (const float*)d_in[2];
    const float* W_in2 = (const float*)d_in[3];
    const float* b_in2 = (const float*)d_in[4];
    const float* W_z   = (const float*)d_in[5];
    const float* b_z   = (const float*)d_in[6];
    const float* W_h   = (const float*)d_in[7];
    const float* b_h   = (const float*)d_in[8];
    const float* W_out = (const float*)d_in[9];
    const float* b_out = (const float*)d_in[10];
    float* out = (float*)d_out;

    __half *xh, *w1h, *w2h, *wzh, *whh, *woh, *xin, *zh, *hth, *xskip, *u;
    float *aggA, *aggB, *carry;
    cudaGetSymbolAddress((void**)&xh, g_xh);
    cudaGetSymbolAddress((void**)&w1h, g_w1h);   cudaGetSymbolAddress((void**)&w2h, g_w2h);
    cudaGetSymbolAddress((void**)&wzh, g_wzh);   cudaGetSymbolAddress((void**)&whh, g_whh);
    cudaGetSymbolAddress((void**)&woh, g_woh);
    cudaGetSymbolAddress((void**)&xin, g_xin);
    cudaGetSymbolAddress((void**)&zh, g_z);      cudaGetSymbolAddress((void**)&hth, g_ht);
    cudaGetSymbolAddress((void**)&xskip, g_xskip);
    cudaGetSymbolAddress((void**)&u, g_u);
    cudaGetSymbolAddress((void**)&aggA, g_aggA); cudaGetSymbolAddress((void**)&aggB, g_aggB);
    cudaGetSymbolAddress((void**)&carry, g_carry);

    cudaFuncSetAttribute(gemm_mma<1,1>, cudaFuncAttributeMaxDynamicSharedMemorySize, SMEM_BYTES);
    cudaFuncSetAttribute(gemm_mma<2,1>, cudaFuncAttributeMaxDynamicSharedMemorySize, SMEM_BYTES);
    cudaFuncSetAttribute(gemm_mma<0,1>, cudaFuncAttributeMaxDynamicSharedMemorySize, SMEM_BYTES);
    cudaFuncSetAttribute(gemm_mma<0,0>, cudaFuncAttributeMaxDynamicSharedMemorySize, SMEM_BYTES);

    // 0: convert x -> fp16
    convert_h<<<(M_TOT * HID + 255) / 256, 256>>>(x, xh, M_TOT * HID);
    // 1: W_in1^T
    transpose_h<<<dim3(EXPD/32, HID/32),  256>>>(W_in1, w1h, HID,  EXPD);
    // 2: W_z^T
    transpose_h<<<dim3(EXPD/32, EXPD/32), 256>>>(W_z,   wzh, EXPD, EXPD);
    // 3: x_in = silu(x@W_in1 + b1) -> fp16
    gemm_mma<1,1><<<dim3(EXPD/BN, M_TOT/BM), NTHREADS, SMEM_BYTES>>>(
        xh, w1h, b_in1, nullptr, xin, M_TOT, EXPD, HID);
    // 4: W_h^T
    transpose_h<<<dim3(EXPD/32, EXPD/32), 256>>>(W_h,   whh, EXPD, EXPD);
    // 5: z = sigmoid(x_in@W_z + bz) -> fp16   <-- ncu samples this launch
    gemm_mma<2,1><<<dim3(EXPD/BN, M_TOT/BM), NTHREADS, SMEM_BYTES>>>(
        xin, wzh, b_z, nullptr, zh, M_TOT, EXPD, EXPD);
    // 6: W_in2^T
    transpose_h<<<dim3(EXPD/32, HID/32),  256>>>(W_in2, w2h, HID,  EXPD);
    // 7: x_skip = silu(x@W_in2 + b2) -> fp16
    gemm_mma<1,1><<<dim3(EXPD/BN, M_TOT/BM), NTHREADS, SMEM_BYTES>>>(
        xh, w2h, b_in2, nullptr, xskip, M_TOT, EXPD, HID);
    // 8: ht = x_in@W_h + bh -> fp16
    gemm_mma<0,1><<<dim3(EXPD/BN, M_TOT/BM), NTHREADS, SMEM_BYTES>>>(
        xin, whh, b_h, nullptr, hth, M_TOT, EXPD, EXPD);
    // 9: W_out^T
    transpose_h<<<dim3(HID/32,  EXPD/32), 256>>>(W_out, woh, EXPD, HID);

    // 10-12: minGRU scan; pass3 fuses u = x_skip + h -> fp16
    int p1 = BATCH * NCH * EXPD;
    scan_pass1<<<p1 / 256, 256>>>(zh, hth, aggA, aggB);
    scan_pass2<<<(BATCH * EXPD) / 256, 256>>>(aggA, aggB, carry);
    scan_pass3<<<p1 / 256, 256>>>(zh, hth, carry, xskip, u);

    // 13: out = u @ W_out + b_out -> fp32
    gemm_mma<0,0><<<dim3(HID/BN, M_TOT/BM), NTHREADS, SMEM_BYTES>>>(
        u, woh, b_out, out, nullptr, M_TOT, HID, EXPD);
}

// round 13
// speedup vs baseline: 1.0713x; 1.0713x over previous
#include <cuda_runtime.h>
#include <cuda_fp16.h>
#include <cstdint>
#include <math.h>

// ---------------- problem dims (fixed) ----------------
#define HID   512
#define EXPD  2048
#define BATCH 4
#define SEQ   4096
#define M_TOT (BATCH*SEQ)      // 16384
#define NCH 64
#define CHL 64

// ---------------- scratch (device globals; 16B aligned) ----------------
__device__ __align__(16) __half g_xh  [(size_t)M_TOT*HID];
__device__ __align__(16) __half g_w1h [(size_t)EXPD*HID];
__device__ __align__(16) __half g_w2h [(size_t)EXPD*HID];
__device__ __align__(16) __half g_wzh [(size_t)EXPD*EXPD];
__device__ __align__(16) __half g_whh [(size_t)EXPD*EXPD];
__device__ __align__(16) __half g_woh [(size_t)HID*EXPD];
__device__ __align__(16) __half g_xin [(size_t)M_TOT*EXPD];
__device__ __align__(16) __half g_z   [(size_t)M_TOT*EXPD];
__device__ __align__(16) __half g_ht  [(size_t)M_TOT*EXPD];
__device__ __align__(16) __half g_xskip[(size_t)M_TOT*EXPD];
__device__ __align__(16) __half g_u   [(size_t)M_TOT*EXPD];
__device__ __align__(16) float g_aggA [(size_t)BATCH*NCH*EXPD];
__device__ __align__(16) float g_aggB [(size_t)BATCH*NCH*EXPD];
__device__ __align__(16) float g_carry[(size_t)BATCH*NCH*EXPD];

// ---------------- PTX helpers (base-target features only) ----------------
__device__ __forceinline__ uint32_t smem_u32(const void* p) {
    uint32_t a;
    asm("{ .reg .u64 t; cvta.to.shared.u64 t, %1; cvt.u32.u64 %0, t; }" : "=r"(a) : "l"(p));
    return a;
}
__device__ __forceinline__ void cp16(uint32_t dst, const void* src) {
    asm volatile("cp.async.cg.shared.global [%0], [%1], 16;" :: "r"(dst), "l"(src));
}
#define CP_COMMIT() asm volatile("cp.async.commit_group;" ::: "memory")
#define CP_WAIT(n)  asm volatile("cp.async.wait_group %0;" :: "n"(n) : "memory")

__device__ __forceinline__ void ldsm4(uint32_t* r, uint32_t addr) {
    asm volatile("ldmatrix.sync.aligned.m8n8.x4.shared.b16 {%0,%1,%2,%3}, [%4];"
        : "=r"(r[0]), "=r"(r[1]), "=r"(r[2]), "=r"(r[3]) : "r"(addr));
}
__device__ __forceinline__ void mma_f16(float* c, const uint32_t* a, const uint32_t* b) {
    asm volatile(
        "mma.sync.aligned.m16n8k16.row.col.f32.f16.f16.f32 "
        "{%0,%1,%2,%3}, {%4,%5,%6,%7}, {%8,%9}, {%0,%1,%2,%3};"
        : "+f"(c[0]), "+f"(c[1]), "+f"(c[2]), "+f"(c[3])
        : "r"(a[0]), "r"(a[1]), "r"(a[2]), "r"(a[3]), "r"(b[0]), "r"(b[1]));
}

// ---------------- mma.sync GEMM: C[M,N] = act(A[M,K] @ (B[N,K])^T + bias) ------
// fp16 x fp16 -> fp32 acc. 256 threads: 8 warps, 4m x 2n, warp tile 32x64.
// 2 CTAs/SM (regs capped at 128, smem 96KB/CTA). R11 inner loop (best measured).
#define BM 128
#define BN 128
#define BK 64
#define NTHREADS 256
#define T_A 0
#define T_B 16384
#define STAGE_BYTES 32768
#define NSTAGE 3
#define SMEM_BYTES (NSTAGE*STAGE_BYTES)

// ACT: 0=none 1=silu 2=sigmoid ; OUT: 0 -> Cf fp32 ; 1 -> Ch fp16
template<int ACT, int OUT>
__global__ __launch_bounds__(NTHREADS, 2)
void gemm_mma(const __half* __restrict__ A, const __half* __restrict__ B,
              const float* __restrict__ bias,
              float* __restrict__ Cf, __half* __restrict__ Ch,
              int M, int N, int K)
{
    extern __shared__ char smem[];
    const uint32_t sb = smem_u32(smem);
    const int tid  = threadIdx.x;
    const int wid  = tid >> 5;
    const int lane = tid & 31;
    const int wm = wid >> 1;           // 0..3  -> m offset wm*32
    const int wn = wid & 1;            // 0..1  -> n offset wn*64
    const int bm = blockIdx.y * BM;
    const int bn = blockIdx.x * BN;

    const int Kv = K >> 3;             // row pitch in uint4 (8 fp16)
    const uint4* gA = (const uint4*)A;
    const uint4* gB = (const uint4*)B;

    const int nk = K / BK;

    auto load_stage = [&](int buf, int kc) {
        const int kv0 = kc * (BK / 8);
        const uint32_t base = sb + buf * STAGE_BYTES;
        #pragma unroll
        for (int t = 0; t < 4; t++) {           // A: 128 rows x 8 chunks
            int i = tid + t * NTHREADS;
            int row = i >> 3, ch = i & 7;
            uint32_t so = (uint32_t)(row * 128 + ((ch ^ (row & 7)) << 4));
            cp16(base + T_A + so, gA + (size_t)(bm + row) * Kv + kv0 + ch);
        }
        #pragma unroll
        for (int t = 0; t < 4; t++) {           // B: 128 rows x 8 chunks
            int i = tid + t * NTHREADS;
            int row = i >> 3, ch = i & 7;
            uint32_t so = (uint32_t)(row * 128 + ((ch ^ (row & 7)) << 4));
            cp16(base + T_B + so, gB + (size_t)(bn + row) * Kv + kv0 + ch);
        }
    };

    float acc[2][8][4];
    #pragma unroll
    for (int mi = 0; mi < 2; mi++)
        #pragma unroll
        for (int ni = 0; ni < 8; ni++)
            #pragma unroll
            for (int q = 0; q < 4; q++)
                acc[mi][ni][q] = 0.f;

    load_stage(0, 0);
    CP_COMMIT();
    load_stage(1, 1);
    CP_COMMIT();

    for (int kc = 0; kc < nk; kc++) {
        const int buf = kc % NSTAGE;
        if (kc + 1 < nk) { CP_WAIT(1); } else { CP_WAIT(0); }
        __syncthreads();
        if (kc + 2 < nk) {
            load_stage((kc + 2) % NSTAGE, kc + 2);
            CP_COMMIT();
        }

        const uint32_t st = sb + buf * STAGE_BYTES;
        #pragma unroll
        for (int kk = 0; kk < BK / 16; kk++) {
            const int byteCol = kk * 32 + ((lane >> 4) << 4);
            uint32_t ah[2][4];
            #pragma unroll
            for (int mi = 0; mi < 2; mi++) {
                int row = wm * 32 + mi * 16 + (lane & 15);
                uint32_t so = (uint32_t)(row * 128 + byteCol) ^ ((uint32_t)(row & 7) << 4);
                ldsm4(ah[mi], st + T_A + so);
            }
            #pragma unroll
            for (int nt = 0; nt < 4; nt++) {
                int row = wn * 64 + nt * 16 + (lane & 15);
                uint32_t so = (uint32_t)(row * 128 + byteCol) ^ ((uint32_t)(row & 7) << 4);
                uint32_t rh[4];
                ldsm4(rh, st + T_B + so);
                uint32_t b0[2] = { rh[0], rh[2] }, b1[2] = { rh[1], rh[3] };
                #pragma unroll
                for (int mi = 0; mi < 2; mi++) {
                    mma_f16(acc[mi][2*nt+0], ah[mi], b0);
                    mma_f16(acc[mi][2*nt+1], ah[mi], b1);
                }
            }
        }
    }

    // ---------------- epilogue: bias + activation + store ----------------
    const int qrow = lane >> 2;        // 0..7
    const int qcol = (lane & 3) * 2;   // 0,2,4,6
    #pragma unroll
    for (int mi = 0; mi < 2; mi++) {
        #pragma unroll
        for (int ni = 0; ni < 8; ni++) {
            const int n0 = bn + wn * 64 + ni * 8 + qcol;
            const float bias0 = bias[n0], bias1 = bias[n0 + 1];
            #pragma unroll
            for (int half_ = 0; half_ < 2; half_++) {
                const int m = bm + wm * 32 + mi * 16 + qrow + half_ * 8;
                float v0 = acc[mi][ni][half_ * 2 + 0] + bias0;
                float v1 = acc[mi][ni][half_ * 2 + 1] + bias1;
                if (ACT == 1) {
                    v0 *= 1.f / (1.f + expf(-v0));
                    v1 *= 1.f / (1.f + expf(-v1));
                } else if (ACT == 2) {
                    v0 = 1.f / (1.f + expf(-v0));
                    v1 = 1.f / (1.f + expf(-v1));
                }
                if (OUT == 1) {
                    __half h0 = __float2half_rn(v0);
                    __half h1 = __float2half_rn(v1);
                    uint32_t hp = (uint32_t)__half_as_ushort(h0) | ((uint32_t)__half_as_ushort(h1) << 16);
                    *(uint32_t*)&Ch[(size_t)m * N + n0] = hp;
                } else {
                    *(float2*)&Cf[(size_t)m * N + n0] = make_float2(v0, v1);
                }
            }
        }
    }
}

// ---------------- weight transpose: W[K,N] fp32 -> T[N,K] fp16 -------------
__global__ __launch_bounds__(256)
void transpose_h(const float* __restrict__ W, __half* __restrict__ T, int K, int N)
{
    __shared__ float t[32][33];
    const int n0 = blockIdx.x * 32, k0 = blockIdx.y * 32;
    const int tx = threadIdx.x & 31, ty0 = threadIdx.x >> 5;
    #pragma unroll
    for (int dy = 0; dy < 32; dy += 8)
        t[ty0 + dy][tx] = W[(size_t)(k0 + ty0 + dy) * N + n0 + tx];
    __syncthreads();
    #pragma unroll
    for (int dy = 0; dy < 32; dy += 8) {
        int ty = ty0 + dy;
        T[(size_t)(n0 + ty) * K + k0 + tx] = __float2half_rn(t[tx][ty]);
    }
}

// ---------------- x convert: fp32 -> fp16 ----------------
__global__ __launch_bounds__(256)
void convert_h(const float* __restrict__ x, __half* __restrict__ h, int n)
{
    int i = blockIdx.x * blockDim.x + threadIdx.x;
    if (i < n) h[i] = __float2half_rn(x[i]);
}

// ---------------- scan (minGRU linear recurrence), 3-pass chunked ----------------
__global__ __launch_bounds__(256)
void scan_pass1(const __half* __restrict__ z, const __half* __restrict__ ht,
                float* __restrict__ aggA, float* __restrict__ aggB)
{
    int t = blockIdx.x * blockDim.x + threadIdx.x;
    int f = t % EXPD, rc = t / EXPD, c = rc % NCH, bb = rc / NCH;
    size_t base = ((size_t)bb * SEQ + (size_t)c * CHL) * EXPD + f;
    float A = 1.f, B = 0.f;
    #pragma unroll 4
    for (int i = 0; i < CHL; i++) {
        size_t idx = base + (size_t)i * EXPD;
        float zi = __half2float(z[idx]), hi = __half2float(ht[idx]);
        float ai = 1.f - zi, bi = zi * hi;
        A = A * ai;
        B = B * ai + bi;
    }
    aggA[t] = A; aggB[t] = B;
}

__global__ __launch_bounds__(256)
void scan_pass2(const float* __restrict__ aggA, const float* __restrict__ aggB,
                float* __restrict__ carry)
{
    int t = blockIdx.x * blockDim.x + threadIdx.x;
    int f = t % EXPD, bb = t / EXPD;
    size_t base = (size_t)bb * NCH * EXPD + f;
    float h = 0.f;
    for (int c = 0; c < NCH; c++) {
        size_t idx = base + (size_t)c * EXPD;
        carry[idx] = h;
        h = aggA[idx] * h + aggB[idx];
    }
}

__global__ __launch_bounds__(256)
void scan_pass3(const __half* __restrict__ z, const __half* __restrict__ ht,
                const float* __restrict__ carry, const __half* __restrict__ xskip,
                __half* __restrict__ u)
{
    int t = blockIdx.x * blockDim.x + threadIdx.x;
    int f = t % EXPD, rc = t / EXPD, c = rc % NCH, bb = rc / NCH;
    size_t base = ((size_t)bb * SEQ + (size_t)c * CHL) * EXPD + f;
    float h = carry[t];
    #pragma unroll 4
    for (int i = 0; i < CHL; i++) {
        size_t idx = base + (size_t)i * EXPD;
        float zi = __half2float(z[idx]), hti = __half2float(ht[idx]);
        h = (1.f - zi) * h + zi * hti;
        u[idx] = __float2half_rn(__half2float(xskip[idx]) + h);
    }
}

// ---------------- launch (stream-overlapped DAG; graph-capturable) ----------------
extern "C" void kernel_launch(void* const* d_in, const int* in_sizes, int n_in,
                              void* d_out, int out_size)
{
    const float* x     = (const float*)d_in[0];
    const float* W_in1 = (const float*)d_in[1];
    const float* b_in1 = (const float*)d_in[2];
    const float* W_in2 = (const float*)d_in[3];
    const float* b_in2 = (const float*)d_in[4];
    const float* W_z   = (const float*)d_in[5];
    const float* b_z   = (const float*)d_in[6];
    const float* W_h   = (const float*)d_in[7];
    const float* b_h   = (const float*)d_in[8];
    const float* W_out = (const float*)d_in[9];
    const float* b_out = (const float*)d_in[10];
    float* out = (float*)d_out;

    __half *xh, *w1h, *w2h, *wzh, *whh, *woh, *xin, *zh, *hth, *xskip, *u;
    float *aggA, *aggB, *carry;
    cudaGetSymbolAddress((void**)&xh, g_xh);
    cudaGetSymbolAddress((void**)&w1h, g_w1h);   cudaGetSymbolAddress((void**)&w2h, g_w2h);
    cudaGetSymbolAddress((void**)&wzh, g_wzh);   cudaGetSymbolAddress((void**)&whh, g_whh);
    cudaGetSymbolAddress((void**)&woh, g_woh);
    cudaGetSymbolAddress((void**)&xin, g_xin);
    cudaGetSymbolAddress((void**)&zh, g_z);      cudaGetSymbolAddress((void**)&hth, g_ht);
    cudaGetSymbolAddress((void**)&xskip, g_xskip);
    cudaGetSymbolAddress((void**)&u, g_u);
    cudaGetSymbolAddress((void**)&aggA, g_aggA); cudaGetSymbolAddress((void**)&aggB, g_aggB);
    cudaGetSymbolAddress((void**)&carry, g_carry);

    cudaFuncSetAttribute(gemm_mma<1,1>, cudaFuncAttributeMaxDynamicSharedMemorySize, SMEM_BYTES);
    cudaFuncSetAttribute(gemm_mma<2,1>, cudaFuncAttributeMaxDynamicSharedMemorySize, SMEM_BYTES);
    cudaFuncSetAttribute(gemm_mma<0,1>, cudaFuncAttributeMaxDynamicSharedMemorySize, SMEM_BYTES);
    cudaFuncSetAttribute(gemm_mma<0,0>, cudaFuncAttributeMaxDynamicSharedMemorySize, SMEM_BYTES);

    // one-time stream/event setup (no device memory involved)
    static cudaStream_t s1 = nullptr, s2 = nullptr;
    static cudaEvent_t ev_root, ev_conv, ev_in1, ev_wh, ev_z, ev_in2, ev_wo;
    if (!s1) {
        cudaStreamCreateWithFlags(&s1, cudaStreamNonBlocking);
        cudaStreamCreateWithFlags(&s2, cudaStreamNonBlocking);
        cudaEventCreateWithFlags(&ev_root, cudaEventDisableTiming);
        cudaEventCreateWithFlags(&ev_conv, cudaEventDisableTiming);
        cudaEventCreateWithFlags(&ev_in1,  cudaEventDisableTiming);
        cudaEventCreateWithFlags(&ev_wh,   cudaEventDisableTiming);
        cudaEventCreateWithFlags(&ev_z,    cudaEventDisableTiming);
        cudaEventCreateWithFlags(&ev_in2,  cudaEventDisableTiming);
        cudaEventCreateWithFlags(&ev_wo,   cudaEventDisableTiming);
    }
    cudaStream_t s0 = 0;   // legacy/capture stream

    // fork side streams off the capture stream
    cudaEventRecord(ev_root, s0);
    cudaStreamWaitEvent(s1, ev_root, 0);
    cudaStreamWaitEvent(s2, ev_root, 0);

    // s0: convert x -> fp16, W_in1^T, in1 GEMM
    convert_h<<<(M_TOT * HID + 255) / 256, 256, 0, s0>>>(x, xh, M_TOT * HID);
    cudaEventRecord(ev_conv, s0);
    transpose_h<<<dim3(EXPD/32, HID/32), 256, 0, s0>>>(W_in1, w1h, HID, EXPD);
    gemm_mma<1,1><<<dim3(EXPD/BN, M_TOT/BM), NTHREADS, SMEM_BYTES, s0>>>(
        xh, w1h, b_in1, nullptr, xin, M_TOT, EXPD, HID);
    cudaEventRecord(ev_in1, s0);

    // s1: W_z^T, W_h^T (independent of x); later z GEMM
    transpose_h<<<dim3(EXPD/32, EXPD/32), 256, 0, s1>>>(W_z, wzh, EXPD, EXPD);
    transpose_h<<<dim3(EXPD/32, EXPD/32), 256, 0, s1>>>(W_h, whh, EXPD, EXPD);
    cudaEventRecord(ev_wh, s1);
    cudaStreamWaitEvent(s1, ev_in1, 0);
    gemm_mma<2,1><<<dim3(EXPD/BN, M_TOT/BM), NTHREADS, SMEM_BYTES, s1>>>(
        xin, wzh, b_z, nullptr, zh, M_TOT, EXPD, EXPD);
    cudaEventRecord(ev_z, s1);

    // s2: W_in2^T, W_out^T, in2 GEMM (needs xh)
    transpose_h<<<dim3(EXPD/32, HID/32), 256, 0, s2>>>(W_in2, w2h, HID, EXPD);
    transpose_h<<<dim3(HID/32, EXPD/32), 256, 0, s2>>>(W_out, woh, EXPD, HID);
    cudaEventRecord(ev_wo, s2);
    cudaStreamWaitEvent(s2, ev_conv, 0);
    gemm_mma<1,1><<<dim3(EXPD/BN, M_TOT/BM), NTHREADS, SMEM_BYTES, s2>>>(
        xh, w2h, b_in2, nullptr, xskip, M_TOT, EXPD, HID);
    cudaEventRecord(ev_in2, s2);

    // s0: ht GEMM (needs xin from s0 + whh from s1) — runs concurrent with z on s1
    cudaStreamWaitEvent(s0, ev_wh, 0);
    gemm_mma<0,1><<<dim3(EXPD/BN, M_TOT/BM), NTHREADS, SMEM_BYTES, s0>>>(
        xin, whh, b_h, nullptr, hth, M_TOT, EXPD, EXPD);

    // s0: scans (join z from s1, xskip from s2)
    cudaStreamWaitEvent(s0, ev_z, 0);
    int p1 = BATCH * NCH * EXPD;
    scan_pass1<<<p1 / 256, 256, 0, s0>>>(zh, hth, aggA, aggB);
    scan_pass2<<<(BATCH * EXPD) / 256, 256, 0, s0>>>(aggA, aggB, carry);
    cudaStreamWaitEvent(s0, ev_in2, 0);
    scan_pass3<<<p1 / 256, 256, 0, s0>>>(zh, hth, carry, xskip, u);

    // s0: out = u @ W_out + b_out (join woh from s2)
    cudaStreamWaitEvent(s0, ev_wo, 0);
    gemm_mma<0,0><<<dim3(HID/BN, M_TOT/BM), NTHREADS, SMEM_BYTES, s0>>>(
        u, woh, b_out, out, nullptr, M_TOT, HID, EXPD);
}

// round 14
// speedup vs baseline: 1.0928x; 1.0200x over previous
#include <cuda_runtime.h>
#include <cuda_fp16.h>
#include <cstdint>
#include <math.h>

// ---------------- problem dims (fixed) ----------------
#define HID   512
#define EXPD  2048
#define BATCH 4
#define SEQ   4096
#define M_TOT (BATCH*SEQ)      // 16384
#define NCH 64
#define CHL 64

// ---------------- scratch (device globals; 16B aligned) ----------------
__device__ __align__(16) __half g_xh  [(size_t)M_TOT*HID];
__device__ __align__(16) __half g_w1h [(size_t)EXPD*HID];
__device__ __align__(16) __half g_w2h [(size_t)EXPD*HID];
__device__ __align__(16) __half g_wzh [(size_t)2*EXPD*EXPD];   // interleaved: row 2f=Wz_f, 2f+1=Wh_f
__device__ __align__(16) __half g_woh [(size_t)HID*EXPD];
__device__ __align__(16) __half g_xin [(size_t)M_TOT*EXPD];
__device__ __align__(16) __half g_zht [(size_t)M_TOT*2*EXPD];  // interleaved (z, ht) pairs
__device__ __align__(16) __half g_xskip[(size_t)M_TOT*EXPD];
__device__ __align__(16) __half g_u   [(size_t)M_TOT*EXPD];
__device__ __align__(16) float g_aggA [(size_t)BATCH*NCH*EXPD];
__device__ __align__(16) float g_aggB [(size_t)BATCH*NCH*EXPD];
__device__ __align__(16) float g_carry[(size_t)BATCH*NCH*EXPD];

// ---------------- PTX helpers (base-target features only) ----------------
__device__ __forceinline__ uint32_t smem_u32(const void* p) {
    uint32_t a;
    asm("{ .reg .u64 t; cvta.to.shared.u64 t, %1; cvt.u32.u64 %0, t; }" : "=r"(a) : "l"(p));
    return a;
}
__device__ __forceinline__ void cp16(uint32_t dst, const void* src) {
    asm volatile("cp.async.cg.shared.global [%0], [%1], 16;" :: "r"(dst), "l"(src));
}
#define CP_COMMIT() asm volatile("cp.async.commit_group;" ::: "memory")
#define CP_WAIT(n)  asm volatile("cp.async.wait_group %0;" :: "n"(n) : "memory")

__device__ __forceinline__ void ldsm4(uint32_t* r, uint32_t addr) {
    asm volatile("ldmatrix.sync.aligned.m8n8.x4.shared.b16 {%0,%1,%2,%3}, [%4];"
        : "=r"(r[0]), "=r"(r[1]), "=r"(r[2]), "=r"(r[3]) : "r"(addr));
}
__device__ __forceinline__ void mma_f16(float* c, const uint32_t* a, const uint32_t* b) {
    asm volatile(
        "mma.sync.aligned.m16n8k16.row.col.f32.f16.f16.f32 "
        "{%0,%1,%2,%3}, {%4,%5,%6,%7}, {%8,%9}, {%0,%1,%2,%3};"
        : "+f"(c[0]), "+f"(c[1]), "+f"(c[2]), "+f"(c[3])
        : "r"(a[0]), "r"(a[1]), "r"(a[2]), "r"(a[3]), "r"(b[0]), "r"(b[1]));
}

// ---------------- mma.sync GEMM ----------------
// MODE 0: Cf fp32, no act (out-proj)
// MODE 1: Ch fp16, silu (in-proj)
// MODE 2: gate-pair — even col v0 -> sigmoid(+bias[f]), odd col v1 -> +bias2[f];
//         packed (z,ht) half2 written as one 32-bit store to Ch (interleaved zht).
#define BM 128
#define BN 128
#define BK 64
#define NTHREADS 256
#define T_A 0
#define T_B 16384
#define STAGE_BYTES 32768
#define NSTAGE 3
#define SMEM_BYTES (NSTAGE*STAGE_BYTES)

template<int MODE>
__global__ __launch_bounds__(NTHREADS, 2)
void gemm_mma(const __half* __restrict__ A, const __half* __restrict__ B,
              const float* __restrict__ bias, const float* __restrict__ bias2,
              float* __restrict__ Cf, __half* __restrict__ Ch,
              int M, int N, int K)
{
    extern __shared__ char smem[];
    const uint32_t sb = smem_u32(smem);
    const int tid  = threadIdx.x;
    const int wid  = tid >> 5;
    const int lane = tid & 31;
    const int wm = wid >> 1;           // 0..3  -> m offset wm*32
    const int wn = wid & 1;            // 0..1  -> n offset wn*64
    const int bm = blockIdx.y * BM;
    const int bn = blockIdx.x * BN;

    const int Kv = K >> 3;             // row pitch in uint4 (8 fp16)
    const uint4* gA = (const uint4*)A;
    const uint4* gB = (const uint4*)B;

    const int nk = K / BK;

    auto load_stage = [&](int buf, int kc) {
        const int kv0 = kc * (BK / 8);
        const uint32_t base = sb + buf * STAGE_BYTES;
        #pragma unroll
        for (int t = 0; t < 4; t++) {           // A: 128 rows x 8 chunks
            int i = tid + t * NTHREADS;
            int row = i >> 3, ch = i & 7;
            uint32_t so = (uint32_t)(row * 128 + ((ch ^ (row & 7)) << 4));
            cp16(base + T_A + so, gA + (size_t)(bm + row) * Kv + kv0 + ch);
        }
        #pragma unroll
        for (int t = 0; t < 4; t++) {           // B: 128 rows x 8 chunks
            int i = tid + t * NTHREADS;
            int row = i >> 3, ch = i & 7;
            uint32_t so = (uint32_t)(row * 128 + ((ch ^ (row & 7)) << 4));
            cp16(base + T_B + so, gB + (size_t)(bn + row) * Kv + kv0 + ch);
        }
    };

    float acc[2][8][4];
    #pragma unroll
    for (int mi = 0; mi < 2; mi++)
        #pragma unroll
        for (int ni = 0; ni < 8; ni++)
            #pragma unroll
            for (int q = 0; q < 4; q++)
                acc[mi][ni][q] = 0.f;

    load_stage(0, 0);
    CP_COMMIT();
    load_stage(1, 1);
    CP_COMMIT();

    for (int kc = 0; kc < nk; kc++) {
        const int buf = kc % NSTAGE;
        if (kc + 1 < nk) { CP_WAIT(1); } else { CP_WAIT(0); }
        __syncthreads();
        if (kc + 2 < nk) {
            load_stage((kc + 2) % NSTAGE, kc + 2);
            CP_COMMIT();
        }

        const uint32_t st = sb + buf * STAGE_BYTES;
        #pragma unroll
        for (int kk = 0; kk < BK / 16; kk++) {
            const int byteCol = kk * 32 + ((lane >> 4) << 4);
            uint32_t ah[2][4];
            #pragma unroll
            for (int mi = 0; mi < 2; mi++) {
                int row = wm * 32 + mi * 16 + (lane & 15);
                uint32_t so = (uint32_t)(row * 128 + byteCol) ^ ((uint32_t)(row & 7) << 4);
                ldsm4(ah[mi], st + T_A + so);
            }
            #pragma unroll
            for (int nt = 0; nt < 4; nt++) {
                int row = wn * 64 + nt * 16 + (lane & 15);
                uint32_t so = (uint32_t)(row * 128 + byteCol) ^ ((uint32_t)(row & 7) << 4);
                uint32_t rh[4];
                ldsm4(rh, st + T_B + so);
                uint32_t b0[2] = { rh[0], rh[2] }, b1[2] = { rh[1], rh[3] };
                #pragma unroll
                for (int mi = 0; mi < 2; mi++) {
                    mma_f16(acc[mi][2*nt+0], ah[mi], b0);
                    mma_f16(acc[mi][2*nt+1], ah[mi], b1);
                }
            }
        }
    }

    // ---------------- epilogue ----------------
    const int qrow = lane >> 2;        // 0..7
    const int qcol = (lane & 3) * 2;   // 0,2,4,6 (always even)
    #pragma unroll
    for (int mi = 0; mi < 2; mi++) {
        #pragma unroll
        for (int ni = 0; ni < 8; ni++) {
            const int n0 = bn + wn * 64 + ni * 8 + qcol;
            float bias0, bias1;
            if (MODE == 2) {
                const int f = n0 >> 1;
                bias0 = bias[f];       // b_z
                bias1 = bias2[f];      // b_h
            } else {
                bias0 = bias[n0];
                bias1 = bias[n0 + 1];
            }
            #pragma unroll
            for (int half_ = 0; half_ < 2; half_++) {
                const int m = bm + wm * 32 + mi * 16 + qrow + half_ * 8;
                float v0 = acc[mi][ni][half_ * 2 + 0] + bias0;
                float v1 = acc[mi][ni][half_ * 2 + 1] + bias1;
                if (MODE == 1) {
                    v0 *= 1.f / (1.f + expf(-v0));
                    v1 *= 1.f / (1.f + expf(-v1));
                } else if (MODE == 2) {
                    v0 = 1.f / (1.f + expf(-v0));   // z = sigmoid ; v1 = ht (no act)
                }
                if (MODE == 0) {
                    *(float2*)&Cf[(size_t)m * N + n0] = make_float2(v0, v1);
                } else {
                    __half h0 = __float2half_rn(v0);
                    __half h1 = __float2half_rn(v1);
                    uint32_t hp = (uint32_t)__half_as_ushort(h0) | ((uint32_t)__half_as_ushort(h1) << 16);
                    *(uint32_t*)&Ch[(size_t)m * N + n0] = hp;
                }
            }
        }
    }
}

// ---------------- weight transpose: W[K,N] fp32 -> T[(n*mult+off), K] fp16 ----------
__global__ __launch_bounds__(256)
void transpose_h(const float* __restrict__ W, __half* __restrict__ T, int K, int N,
                 int mult, int off)
{
    __shared__ float t[32][33];
    const int n0 = blockIdx.x * 32, k0 = blockIdx.y * 32;
    const int tx = threadIdx.x & 31, ty0 = threadIdx.x >> 5;
    #pragma unroll
    for (int dy = 0; dy < 32; dy += 8)
        t[ty0 + dy][tx] = W[(size_t)(k0 + ty0 + dy) * N + n0 + tx];
    __syncthreads();
    #pragma unroll
    for (int dy = 0; dy < 32; dy += 8) {
        int ty = ty0 + dy;
        T[(size_t)((n0 + ty) * mult + off) * K + k0 + tx] = __float2half_rn(t[tx][ty]);
    }
}

// ---------------- x convert: fp32 -> fp16 ----------------
__global__ __launch_bounds__(256)
void convert_h(const float* __restrict__ x, __half* __restrict__ h, int n)
{
    int i = blockIdx.x * blockDim.x + threadIdx.x;
    if (i < n) h[i] = __float2half_rn(x[i]);
}

// ---------------- scan (minGRU linear recurrence), 3-pass chunked -----------
// zht holds interleaved (z, ht) pairs: one 32-bit load per step.
__global__ __launch_bounds__(256)
void scan_pass1(const __half* __restrict__ zht,
                float* __restrict__ aggA, float* __restrict__ aggB)
{
    int t = blockIdx.x * blockDim.x + threadIdx.x;
    int f = t % EXPD, rc = t / EXPD, c = rc % NCH, bb = rc / NCH;
    size_t base = ((size_t)bb * SEQ + (size_t)c * CHL) * (2 * EXPD) + 2 * f;
    float A = 1.f, B = 0.f;
    #pragma unroll 4
    for (int i = 0; i < CHL; i++) {
        __half2 p = *(const __half2*)(zht + base + (size_t)i * (2 * EXPD));
        float zi = __half2float(__low2half(p)), hi = __half2float(__high2half(p));
        float ai = 1.f - zi, bi = zi * hi;
        A = A * ai;
        B = B * ai + bi;
    }
    aggA[t] = A; aggB[t] = B;
}

__global__ __launch_bounds__(256)
void scan_pass2(const float* __restrict__ aggA, const float* __restrict__ aggB,
                float* __restrict__ carry)
{
    int t = blockIdx.x * blockDim.x + threadIdx.x;
    int f = t % EXPD, bb = t / EXPD;
    size_t base = (size_t)bb * NCH * EXPD + f;
    float h = 0.f;
    for (int c = 0; c < NCH; c++) {
        size_t idx = base + (size_t)c * EXPD;
        carry[idx] = h;
        h = aggA[idx] * h + aggB[idx];
    }
}

__global__ __launch_bounds__(256)
void scan_pass3(const __half* __restrict__ zht,
                const float* __restrict__ carry, const __half* __restrict__ xskip,
                __half* __restrict__ u)
{
    int t = blockIdx.x * blockDim.x + threadIdx.x;
    int f = t % EXPD, rc = t / EXPD, c = rc % NCH, bb = rc / NCH;
    size_t row0 = (size_t)bb * SEQ + (size_t)c * CHL;
    size_t basez = row0 * (2 * EXPD) + 2 * f;
    size_t baseu = row0 * EXPD + f;
    float h = carry[t];
    #pragma unroll 4
    for (int i = 0; i < CHL; i++) {
        __half2 p = *(const __half2*)(zht + basez + (size_t)i * (2 * EXPD));
        float zi = __half2float(__low2half(p)), hti = __half2float(__high2half(p));
        h = (1.f - zi) * h + zi * hti;
        size_t iu = baseu + (size_t)i * EXPD;
        u[iu] = __float2half_rn(__half2float(xskip[iu]) + h);
    }
}

// ---------------- launch (stream-overlapped DAG; graph-capturable) ----------------
extern "C" void kernel_launch(void* const* d_in, const int* in_sizes, int n_in,
                              void* d_out, int out_size)
{
    const float* x     = (const float*)d_in[0];
    const float* W_in1 = (const float*)d_in[1];
    const float* b_in1 = (const float*)d_in[2];
    const float* W_in2 = (const float*)d_in[3];
    const float* b_in2 = (const float*)d_in[4];
    const float* W_z   = (const float*)d_in[5];
    const float* b_z   = (const float*)d_in[6];
    const float* W_h   = (const float*)d_in[7];
    const float* b_h   = (const float*)d_in[8];
    const float* W_out = (const float*)d_in[9];
    const float* b_out = (const float*)d_in[10];
    float* out = (float*)d_out;

    __half *xh, *w1h, *w2h, *wzh, *woh, *xin, *zht, *xskip, *u;
    float *aggA, *aggB, *carry;
    cudaGetSymbolAddress((void**)&xh, g_xh);
    cudaGetSymbolAddress((void**)&w1h, g_w1h);   cudaGetSymbolAddress((void**)&w2h, g_w2h);
    cudaGetSymbolAddress((void**)&wzh, g_wzh);   cudaGetSymbolAddress((void**)&woh, g_woh);
    cudaGetSymbolAddress((void**)&xin, g_xin);
    cudaGetSymbolAddress((void**)&zht, g_zht);
    cudaGetSymbolAddress((void**)&xskip, g_xskip);
    cudaGetSymbolAddress((void**)&u, g_u);
    cudaGetSymbolAddress((void**)&aggA, g_aggA); cudaGetSymbolAddress((void**)&aggB, g_aggB);
    cudaGetSymbolAddress((void**)&carry, g_carry);

    cudaFuncSetAttribute(gemm_mma<0>, cudaFuncAttributeMaxDynamicSharedMemorySize, SMEM_BYTES);
    cudaFuncSetAttribute(gemm_mma<1>, cudaFuncAttributeMaxDynamicSharedMemorySize, SMEM_BYTES);
    cudaFuncSetAttribute(gemm_mma<2>, cudaFuncAttributeMaxDynamicSharedMemorySize, SMEM_BYTES);

    // one-time stream/event setup (no device memory involved)
    static cudaStream_t s1 = nullptr, s2 = nullptr;
    static cudaEvent_t ev_root, ev_conv, ev_in1, ev_w1, ev_wzh, ev_in2, ev_wo;
    if (!s1) {
        cudaStreamCreateWithFlags(&s1, cudaStreamNonBlocking);
        cudaStreamCreateWithFlags(&s2, cudaStreamNonBlocking);
        cudaEventCreateWithFlags(&ev_root, cudaEventDisableTiming);
        cudaEventCreateWithFlags(&ev_conv, cudaEventDisableTiming);
        cudaEventCreateWithFlags(&ev_in1,  cudaEventDisableTiming);
        cudaEventCreateWithFlags(&ev_w1,   cudaEventDisableTiming);
        cudaEventCreateWithFlags(&ev_wzh,  cudaEventDisableTiming);
        cudaEventCreateWithFlags(&ev_in2,  cudaEventDisableTiming);
        cudaEventCreateWithFlags(&ev_wo,   cudaEventDisableTiming);
    }
    cudaStream_t s0 = 0;   // legacy/capture stream

    cudaEventRecord(ev_root, s0);
    cudaStreamWaitEvent(s1, ev_root, 0);
    cudaStreamWaitEvent(s2, ev_root, 0);

    // s1: W_in1^T, then interleaved W_z/W_h transpose into wzh
    transpose_h<<<dim3(EXPD/32, HID/32), 256, 0, s1>>>(W_in1, w1h, HID, EXPD, 1, 0);
    cudaEventRecord(ev_w1, s1);
    transpose_h<<<dim3(EXPD/32, EXPD/32), 256, 0, s1>>>(W_z, wzh, EXPD, EXPD, 2, 0);
    transpose_h<<<dim3(EXPD/32, EXPD/32), 256, 0, s1>>>(W_h, wzh, EXPD, EXPD, 2, 1);
    cudaEventRecord(ev_wzh, s1);

    // s2: W_in2^T, W_out^T, then in2 GEMM (needs xh)
    transpose_h<<<dim3(EXPD/32, HID/32), 256, 0, s2>>>(W_in2, w2h, HID, EXPD, 1, 0);
    transpose_h<<<dim3(HID/32, EXPD/32), 256, 0, s2>>>(W_out, woh, EXPD, HID, 1, 0);
    cudaEventRecord(ev_wo, s2);

    // s0: convert x, then in1 GEMM
    convert_h<<<(M_TOT * HID + 255) / 256, 256, 0, s0>>>(x, xh, M_TOT * HID);
    cudaEventRecord(ev_conv, s0);
    cudaStreamWaitEvent(s0, ev_w1, 0);
    gemm_mma<1><<<dim3(EXPD/BN, M_TOT/BM), NTHREADS, SMEM_BYTES, s0>>>(
        xh, w1h, b_in1, nullptr, nullptr, xin, M_TOT, EXPD, HID);
    cudaEventRecord(ev_in1, s0);

    // s2: in2 GEMM (needs xh) — overlaps the gate GEMM
    cudaStreamWaitEvent(s2, ev_conv, 0);
    gemm_mma<1><<<dim3(EXPD/BN, M_TOT/BM), NTHREADS, SMEM_BYTES, s2>>>(
        xh, w2h, b_in2, nullptr, nullptr, xskip, M_TOT, EXPD, HID);
    cudaEventRecord(ev_in2, s2);

    // s0: fused gate GEMM (N = 2*EXPD, interleaved zht output)
    cudaStreamWaitEvent(s0, ev_wzh, 0);
    gemm_mma<2><<<dim3(2*EXPD/BN, M_TOT/BM), NTHREADS, SMEM_BYTES, s0>>>(
        xin, wzh, b_z, b_h, nullptr, zht, M_TOT, 2*EXPD, EXPD);

    // s0: scans
    int p1 = BATCH * NCH * EXPD;
    scan_pass1<<<p1 / 256, 256, 0, s0>>>(zht, aggA, aggB);
    scan_pass2<<<(BATCH * EXPD) / 256, 256, 0, s0>>>(aggA, aggB, carry);
    cudaStreamWaitEvent(s0, ev_in2, 0);
    scan_pass3<<<p1 / 256, 256, 0, s0>>>(zht, carry, xskip, u);

    // s0: out = u @ W_out + b_out
    cudaStreamWaitEvent(s0, ev_wo, 0);
    gemm_mma<0><<<dim3(HID/BN, M_TOT/BM), NTHREADS, SMEM_BYTES, s0>>>(
        u, woh, b_out, nullptr, out, nullptr, M_TOT, HID, EXPD);
}

// round 15
// speedup vs baseline: 1.1073x; 1.0133x over previous
#include <cuda_runtime.h>
#include <cuda_fp16.h>
#include <cstdint>
#include <math.h>

// ---------------- problem dims (fixed) ----------------
#define HID   512
#define EXPD  2048
#define BATCH 4
#define SEQ   4096
#define M_TOT (BATCH*SEQ)      // 16384
#define HM    (M_TOT/2)        // 8192 (batches 0-1 / 2-3)
#define NCH 64
#define CHL 64

// ---------------- scratch (device globals; 16B aligned) ----------------
__device__ __align__(16) __half g_xh  [(size_t)M_TOT*HID];
__device__ __align__(16) __half g_w1h [(size_t)EXPD*HID];
__device__ __align__(16) __half g_w2h [(size_t)EXPD*HID];
__device__ __align__(16) __half g_wzh [(size_t)2*EXPD*EXPD];   // interleaved: row 2f=Wz_f, 2f+1=Wh_f
__device__ __align__(16) __half g_woh [(size_t)HID*EXPD];
__device__ __align__(16) __half g_xin [(size_t)M_TOT*EXPD];
__device__ __align__(16) __half g_zht [(size_t)M_TOT*2*EXPD];  // interleaved (z, ht) pairs
__device__ __align__(16) __half g_xskip[(size_t)M_TOT*EXPD];
__device__ __align__(16) __half g_u   [(size_t)M_TOT*EXPD];
__device__ __align__(16) float g_aggA [(size_t)BATCH*NCH*EXPD];
__device__ __align__(16) float g_aggB [(size_t)BATCH*NCH*EXPD];
__device__ __align__(16) float g_carry[(size_t)BATCH*NCH*EXPD];

// ---------------- PTX helpers (base-target features only) ----------------
__device__ __forceinline__ uint32_t smem_u32(const void* p) {
    uint32_t a;
    asm("{ .reg .u64 t; cvta.to.shared.u64 t, %1; cvt.u32.u64 %0, t; }" : "=r"(a) : "l"(p));
    return a;
}
__device__ __forceinline__ void cp16(uint32_t dst, const void* src) {
    asm volatile("cp.async.cg.shared.global [%0], [%1], 16;" :: "r"(dst), "l"(src));
}
#define CP_COMMIT() asm volatile("cp.async.commit_group;" ::: "memory")
#define CP_WAIT(n)  asm volatile("cp.async.wait_group %0;" :: "n"(n) : "memory")

__device__ __forceinline__ void ldsm4(uint32_t* r, uint32_t addr) {
    asm volatile("ldmatrix.sync.aligned.m8n8.x4.shared.b16 {%0,%1,%2,%3}, [%4];"
        : "=r"(r[0]), "=r"(r[1]), "=r"(r[2]), "=r"(r[3]) : "r"(addr));
}
__device__ __forceinline__ void mma_f16(float* c, const uint32_t* a, const uint32_t* b) {
    asm volatile(
        "mma.sync.aligned.m16n8k16.row.col.f32.f16.f16.f32 "
        "{%0,%1,%2,%3}, {%4,%5,%6,%7}, {%8,%9}, {%0,%1,%2,%3};"
        : "+f"(c[0]), "+f"(c[1]), "+f"(c[2]), "+f"(c[3])
        : "r"(a[0]), "r"(a[1]), "r"(a[2]), "r"(a[3]), "r"(b[0]), "r"(b[1]));
}

// ---------------- mma.sync GEMM ----------------
// MODE 0: Cf fp32, no act (out-proj)
// MODE 1: Ch fp16, silu (in-proj)
// MODE 2: gate-pair — even col v0 -> sigmoid(+bias[f]), odd col v1 -> +bias2[f];
//         packed (z,ht) half2 written as one 32-bit store to Ch (interleaved zht).
#define BM 128
#define BN 128
#define BK 64
#define NTHREADS 256
#define T_A 0
#define T_B 16384
#define STAGE_BYTES 32768
#define NSTAGE 3
#define SMEM_BYTES (NSTAGE*STAGE_BYTES)

template<int MODE>
__global__ __launch_bounds__(NTHREADS, 2)
void gemm_mma(const __half* __restrict__ A, const __half* __restrict__ B,
              const float* __restrict__ bias, const float* __restrict__ bias2,
              float* __restrict__ Cf, __half* __restrict__ Ch,
              int M, int N, int K)
{
    extern __shared__ char smem[];
    const uint32_t sb = smem_u32(smem);
    const int tid  = threadIdx.x;
    const int wid  = tid >> 5;
    const int lane = tid & 31;
    const int wm = wid >> 1;           // 0..3  -> m offset wm*32
    const int wn = wid & 1;            // 0..1  -> n offset wn*64
    const int bm = blockIdx.y * BM;
    const int bn = blockIdx.x * BN;

    const int Kv = K >> 3;             // row pitch in uint4 (8 fp16)
    const uint4* gA = (const uint4*)A;
    const uint4* gB = (const uint4*)B;

    const int nk = K / BK;

    auto load_stage = [&](int buf, int kc) {
        const int kv0 = kc * (BK / 8);
        const uint32_t base = sb + buf * STAGE_BYTES;
        #pragma unroll
        for (int t = 0; t < 4; t++) {           // A: 128 rows x 8 chunks
            int i = tid + t * NTHREADS;
            int row = i >> 3, ch = i & 7;
            uint32_t so = (uint32_t)(row * 128 + ((ch ^ (row & 7)) << 4));
            cp16(base + T_A + so, gA + (size_t)(bm + row) * Kv + kv0 + ch);
        }
        #pragma unroll
        for (int t = 0; t < 4; t++) {           // B: 128 rows x 8 chunks
            int i = tid + t * NTHREADS;
            int row = i >> 3, ch = i & 7;
            uint32_t so = (uint32_t)(row * 128 + ((ch ^ (row & 7)) << 4));
            cp16(base + T_B + so, gB + (size_t)(bn + row) * Kv + kv0 + ch);
        }
    };

    float acc[2][8][4];
    #pragma unroll
    for (int mi = 0; mi < 2; mi++)
        #pragma unroll
        for (int ni = 0; ni < 8; ni++)
            #pragma unroll
            for (int q = 0; q < 4; q++)
                acc[mi][ni][q] = 0.f;

    load_stage(0, 0);
    CP_COMMIT();
    load_stage(1, 1);
    CP_COMMIT();

    for (int kc = 0; kc < nk; kc++) {
        const int buf = kc % NSTAGE;
        if (kc + 1 < nk) { CP_WAIT(1); } else { CP_WAIT(0); }
        __syncthreads();
        if (kc + 2 < nk) {
            load_stage((kc + 2) % NSTAGE, kc + 2);
            CP_COMMIT();
        }

        const uint32_t st = sb + buf * STAGE_BYTES;
        #pragma unroll
        for (int kk = 0; kk < BK / 16; kk++) {
            const int byteCol = kk * 32 + ((lane >> 4) << 4);
            uint32_t ah[2][4];
            #pragma unroll
            for (int mi = 0; mi < 2; mi++) {
                int row = wm * 32 + mi * 16 + (lane & 15);
                uint32_t so = (uint32_t)(row * 128 + byteCol) ^ ((uint32_t)(row & 7) << 4);
                ldsm4(ah[mi], st + T_A + so);
            }
            #pragma unroll
            for (int nt = 0; nt < 4; nt++) {
                int row = wn * 64 + nt * 16 + (lane & 15);
                uint32_t so = (uint32_t)(row * 128 + byteCol) ^ ((uint32_t)(row & 7) << 4);
                uint32_t rh[4];
                ldsm4(rh, st + T_B + so);
                uint32_t b0[2] = { rh[0], rh[2] }, b1[2] = { rh[1], rh[3] };
                #pragma unroll
                for (int mi = 0; mi < 2; mi++) {
                    mma_f16(acc[mi][2*nt+0], ah[mi], b0);
                    mma_f16(acc[mi][2*nt+1], ah[mi], b1);
                }
            }
        }
    }

    // ---------------- epilogue ----------------
    const int qrow = lane >> 2;        // 0..7
    const int qcol = (lane & 3) * 2;   // 0,2,4,6 (always even)
    #pragma unroll
    for (int mi = 0; mi < 2; mi++) {
        #pragma unroll
        for (int ni = 0; ni < 8; ni++) {
            const int n0 = bn + wn * 64 + ni * 8 + qcol;
            float bias0, bias1;
            if (MODE == 2) {
                const int f = n0 >> 1;
                bias0 = bias[f];       // b_z
                bias1 = bias2[f];      // b_h
            } else {
                bias0 = bias[n0];
                bias1 = bias[n0 + 1];
            }
            #pragma unroll
            for (int half_ = 0; half_ < 2; half_++) {
                const int m = bm + wm * 32 + mi * 16 + qrow + half_ * 8;
                float v0 = acc[mi][ni][half_ * 2 + 0] + bias0;
                float v1 = acc[mi][ni][half_ * 2 + 1] + bias1;
                if (MODE == 1) {
                    v0 *= 1.f / (1.f + expf(-v0));
                    v1 *= 1.f / (1.f + expf(-v1));
                } else if (MODE == 2) {
                    v0 = 1.f / (1.f + expf(-v0));   // z = sigmoid ; v1 = ht (no act)
                }
                if (MODE == 0) {
                    *(float2*)&Cf[(size_t)m * N + n0] = make_float2(v0, v1);
                } else {
                    __half h0 = __float2half_rn(v0);
                    __half h1 = __float2half_rn(v1);
                    uint32_t hp = (uint32_t)__half_as_ushort(h0) | ((uint32_t)__half_as_ushort(h1) << 16);
                    *(uint32_t*)&Ch[(size_t)m * N + n0] = hp;
                }
            }
        }
    }
}

// ---------------- weight transpose: W[K,N] fp32 -> T[(n*mult+off), K] fp16 ----------
__global__ __launch_bounds__(256)
void transpose_h(const float* __restrict__ W, __half* __restrict__ T, int K, int N,
                 int mult, int off)
{
    __shared__ float t[32][33];
    const int n0 = blockIdx.x * 32, k0 = blockIdx.y * 32;
    const int tx = threadIdx.x & 31, ty0 = threadIdx.x >> 5;
    #pragma unroll
    for (int dy = 0; dy < 32; dy += 8)
        t[ty0 + dy][tx] = W[(size_t)(k0 + ty0 + dy) * N + n0 + tx];
    __syncthreads();
    #pragma unroll
    for (int dy = 0; dy < 32; dy += 8) {
        int ty = ty0 + dy;
        T[(size_t)((n0 + ty) * mult + off) * K + k0 + tx] = __float2half_rn(t[tx][ty]);
    }
}

// ---------------- x convert: fp32 -> fp16 ----------------
__global__ __launch_bounds__(256)
void convert_h(const float* __restrict__ x, __half* __restrict__ h, int n)
{
    int i = blockIdx.x * blockDim.x + threadIdx.x;
    if (i < n) h[i] = __float2half_rn(x[i]);
}

// ---------------- scan (minGRU), 3-pass chunked; bb0 = first batch of this launch ------
__global__ __launch_bounds__(256)
void scan_pass1(const __half* __restrict__ zht,
                float* __restrict__ aggA, float* __restrict__ aggB, int bb0)
{
    int t = blockIdx.x * blockDim.x + threadIdx.x;      // over 2 batches
    int f = t % EXPD, rc = t / EXPD, c = rc % NCH, bb = bb0 + rc / NCH;
    size_t base = ((size_t)bb * SEQ + (size_t)c * CHL) * (2 * EXPD) + 2 * f;
    float A = 1.f, B = 0.f;
    #pragma unroll 4
    for (int i = 0; i < CHL; i++) {
        __half2 p = *(const __half2*)(zht + base + (size_t)i * (2 * EXPD));
        float zi = __half2float(__low2half(p)), hi = __half2float(__high2half(p));
        float ai = 1.f - zi, bi = zi * hi;
        A = A * ai;
        B = B * ai + bi;
    }
    size_t tg = (size_t)t + (size_t)bb0 * NCH * EXPD;
    aggA[tg] = A; aggB[tg] = B;
}

__global__ __launch_bounds__(256)
void scan_pass2(const float* __restrict__ aggA, const float* __restrict__ aggB,
                float* __restrict__ carry, int bb0)
{
    int t = blockIdx.x * blockDim.x + threadIdx.x;      // over 2 batches
    int f = t % EXPD, bb = bb0 + t / EXPD;
    size_t base = (size_t)bb * NCH * EXPD + f;
    float h = 0.f;
    for (int c = 0; c < NCH; c++) {
        size_t idx = base + (size_t)c * EXPD;
        carry[idx] = h;
        h = aggA[idx] * h + aggB[idx];
    }
}

__global__ __launch_bounds__(256)
void scan_pass3(const __half* __restrict__ zht,
                const float* __restrict__ carry, const __half* __restrict__ xskip,
                __half* __restrict__ u, int bb0)
{
    int t = blockIdx.x * blockDim.x + threadIdx.x;      // over 2 batches
    int f = t % EXPD, rc = t / EXPD, c = rc % NCH, bb = bb0 + rc / NCH;
    size_t row0 = (size_t)bb * SEQ + (size_t)c * CHL;
    size_t basez = row0 * (2 * EXPD) + 2 * f;
    size_t baseu = row0 * EXPD + f;
    float h = carry[(size_t)t + (size_t)bb0 * NCH * EXPD];
    #pragma unroll 4
    for (int i = 0; i < CHL; i++) {
        __half2 p = *(const __half2*)(zht + basez + (size_t)i * (2 * EXPD));
        float zi = __half2float(__low2half(p)), hti = __half2float(__high2half(p));
        h = (1.f - zi) * h + zi * hti;
        size_t iu = baseu + (size_t)i * EXPD;
        u[iu] = __float2half_rn(__half2float(xskip[iu]) + h);
    }
}

// ---------------- launch (chunked, stream-overlapped DAG; graph-capturable) ------------
extern "C" void kernel_launch(void* const* d_in, const int* in_sizes, int n_in,
                              void* d_out, int out_size)
{
    const float* x     = (const float*)d_in[0];
    const float* W_in1 = (const float*)d_in[1];
    const float* b_in1 = (const float*)d_in[2];
    const float* W_in2 = (const float*)d_in[3];
    const float* b_in2 = (const float*)d_in[4];
    const float* W_z   = (const float*)d_in[5];
    const float* b_z   = (const float*)d_in[6];
    const float* W_h   = (const float*)d_in[7];
    const float* b_h   = (const float*)d_in[8];
    const float* W_out = (const float*)d_in[9];
    const float* b_out = (const float*)d_in[10];
    float* out = (float*)d_out;

    __half *xh, *w1h, *w2h, *wzh, *woh, *xin, *zht, *xskip, *u;
    float *aggA, *aggB, *carry;
    cudaGetSymbolAddress((void**)&xh, g_xh);
    cudaGetSymbolAddress((void**)&w1h, g_w1h);   cudaGetSymbolAddress((void**)&w2h, g_w2h);
    cudaGetSymbolAddress((void**)&wzh, g_wzh);   cudaGetSymbolAddress((void**)&woh, g_woh);
    cudaGetSymbolAddress((void**)&xin, g_xin);
    cudaGetSymbolAddress((void**)&zht, g_zht);
    cudaGetSymbolAddress((void**)&xskip, g_xskip);
    cudaGetSymbolAddress((void**)&u, g_u);
    cudaGetSymbolAddress((void**)&aggA, g_aggA); cudaGetSymbolAddress((void**)&aggB, g_aggB);
    cudaGetSymbolAddress((void**)&carry, g_carry);

    cudaFuncSetAttribute(gemm_mma<0>, cudaFuncAttributeMaxDynamicSharedMemorySize, SMEM_BYTES);
    cudaFuncSetAttribute(gemm_mma<1>, cudaFuncAttributeMaxDynamicSharedMemorySize, SMEM_BYTES);
    cudaFuncSetAttribute(gemm_mma<2>, cudaFuncAttributeMaxDynamicSharedMemorySize, SMEM_BYTES);

    static cudaStream_t s1 = nullptr, s2 = nullptr;
    static cudaEvent_t ev_root, ev_conv, ev_w1, ev_wzh, ev_in1c1, ev_in2, ev_wo,
                       ev_gate0, ev_out0;
    if (!s1) {
        cudaStreamCreateWithFlags(&s1, cudaStreamNonBlocking);
        cudaStreamCreateWithFlags(&s2, cudaStreamNonBlocking);
        cudaEventCreateWithFlags(&ev_root,  cudaEventDisableTiming);
        cudaEventCreateWithFlags(&ev_conv,  cudaEventDisableTiming);
        cudaEventCreateWithFlags(&ev_w1,    cudaEventDisableTiming);
        cudaEventCreateWithFlags(&ev_wzh,   cudaEventDisableTiming);
        cudaEventCreateWithFlags(&ev_in1c1, cudaEventDisableTiming);
        cudaEventCreateWithFlags(&ev_in2,   cudaEventDisableTiming);
        cudaEventCreateWithFlags(&ev_wo,    cudaEventDisableTiming);
        cudaEventCreateWithFlags(&ev_gate0, cudaEventDisableTiming);
        cudaEventCreateWithFlags(&ev_out0,  cudaEventDisableTiming);
    }
    cudaStream_t s0 = 0;   // legacy/capture stream

    cudaEventRecord(ev_root, s0);
    cudaStreamWaitEvent(s1, ev_root, 0);
    cudaStreamWaitEvent(s2, ev_root, 0);

    // s1: W_in1^T, interleaved W_z/W_h transpose
    transpose_h<<<dim3(EXPD/32, HID/32), 256, 0, s1>>>(W_in1, w1h, HID, EXPD, 1, 0);
    cudaEventRecord(ev_w1, s1);
    transpose_h<<<dim3(EXPD/32, EXPD/32), 256, 0, s1>>>(W_z, wzh, EXPD, EXPD, 2, 0);
    transpose_h<<<dim3(EXPD/32, EXPD/32), 256, 0, s1>>>(W_h, wzh, EXPD, EXPD, 2, 1);
    cudaEventRecord(ev_wzh, s1);

    // s2: W_in2^T, W_out^T
    transpose_h<<<dim3(EXPD/32, HID/32), 256, 0, s2>>>(W_in2, w2h, HID, EXPD, 1, 0);
    transpose_h<<<dim3(HID/32, EXPD/32), 256, 0, s2>>>(W_out, woh, EXPD, HID, 1, 0);
    cudaEventRecord(ev_wo, s2);

    // s0: convert x, in1 on half0
    convert_h<<<(M_TOT * HID + 255) / 256, 256, 0, s0>>>(x, xh, M_TOT * HID);
    cudaEventRecord(ev_conv, s0);
    cudaStreamWaitEvent(s0, ev_w1, 0);
    gemm_mma<1><<<dim3(EXPD/BN, HM/BM), NTHREADS, SMEM_BYTES, s0>>>(
        xh, w1h, b_in1, nullptr, nullptr, xin, HM, EXPD, HID);

    // s1: in1 on half1 (after wzh transposes; needs xh)
    cudaStreamWaitEvent(s1, ev_conv, 0);
    gemm_mma<1><<<dim3(EXPD/BN, HM/BM), NTHREADS, SMEM_BYTES, s1>>>(
        xh + (size_t)HM * HID, w1h, b_in1, nullptr, nullptr,
        xin + (size_t)HM * EXPD, HM, EXPD, HID);
    cudaEventRecord(ev_in1c1, s1);

    // s2: in2 GEMM (full M; needs xh)
    cudaStreamWaitEvent(s2, ev_conv, 0);
    gemm_mma<1><<<dim3(EXPD/BN, M_TOT/BM), NTHREADS, SMEM_BYTES, s2>>>(
        xh, w2h, b_in2, nullptr, nullptr, xskip, M_TOT, EXPD, HID);
    cudaEventRecord(ev_in2, s2);

    // s0: gate half0, then gate half1
    cudaStreamWaitEvent(s0, ev_wzh, 0);
    gemm_mma<2><<<dim3(2*EXPD/BN, HM/BM), NTHREADS, SMEM_BYTES, s0>>>(
        xin, wzh, b_z, b_h, nullptr, zht, HM, 2*EXPD, EXPD);
    cudaEventRecord(ev_gate0, s0);
    cudaStreamWaitEvent(s0, ev_in1c1, 0);
    gemm_mma<2><<<dim3(2*EXPD/BN, HM/BM), NTHREADS, SMEM_BYTES, s0>>>(
        xin + (size_t)HM * EXPD, wzh, b_z, b_h, nullptr,
        zht + (size_t)HM * 2 * EXPD, HM, 2*EXPD, EXPD);

    // s2: scan + out for batches 0-1 (overlaps gate half1 on s0)
    const int p1h = 2 * NCH * EXPD;      // threads per 2 batches
    cudaStreamWaitEvent(s2, ev_gate0, 0);
    scan_pass1<<<p1h / 256, 256, 0, s2>>>(zht, aggA, aggB, 0);
    scan_pass2<<<(2 * EXPD) / 256, 256, 0, s2>>>(aggA, aggB, carry, 0);
    scan_pass3<<<p1h / 256, 256, 0, s2>>>(zht, carry, xskip, u, 0);   // xskip ready (s2 in-order after in2)
    gemm_mma<0><<<dim3(HID/BN, HM/BM), NTHREADS, SMEM_BYTES, s2>>>(
        u, woh, b_out, nullptr, out, nullptr, HM, HID, EXPD);
    cudaEventRecord(ev_out0, s2);

    // s0: scan + out for batches 2-3 (out half0 on s2 overlaps this scan)
    scan_pass1<<<p1h / 256, 256, 0, s0>>>(zht, aggA, aggB, 2);
    scan_pass2<<<(2 * EXPD) / 256, 256, 0, s0>>>(aggA, aggB, carry, 2);
    cudaStreamWaitEvent(s0, ev_in2, 0);
    scan_pass3<<<p1h / 256, 256, 0, s0>>>(zht, carry, xskip, u, 2);
    cudaStreamWaitEvent(s0, ev_wo, 0);
    gemm_mma<0><<<dim3(HID/BN, HM/BM), NTHREADS, SMEM_BYTES, s0>>>(
        u + (size_t)HM * EXPD, woh, b_out, nullptr,
        out + (size_t)HM * HID, nullptr, HM, HID, EXPD);

    // join side streams back into capture stream
    cudaStreamWaitEvent(s0, ev_out0, 0);
}